// round 11
// baseline (speedup 1.0000x reference)
#include <cuda_runtime.h>
#include <cstdint>
#include <cstddef>

#define N 8192
#define D 64

// ---- k2 config ----
#define JS 8                   // j-splits for gather/partials
#define JRANGE (N / JS)        // 1024
#define CJ 128                 // j's per gather chunk
#define NCHUNK (JRANGE / CJ)   // 8 chunks per gather CTA
#define TIB 128                // gather: A-columns per CTA

// ---- k2a (TMA scan) config ----
#define SROWS 32               // rows per scan CTA (one 32-j chunk)
#define SCOLS 4096             // columns per scan CTA
#define SEG_BYTES (SCOLS * 4)  // 16 KB per row-segment transfer
#define NC32 (N / 32)          // 256 chunk32's

// scratch (static device arrays: allocation-free per harness rules)
__device__ float g_y[N * D];                 // y = x@W_nobj + b_nobj (2 MB)
__device__ float g_part[JS][N * D];          // j-split partials (16.8 MB)
__device__ unsigned g_mask32[NC32 * N];      // bit j%32 of A[j][i], per (j/32, i) (8.4 MB)

// ---------------------------------------------------------------------------
// mbarrier / TMA-bulk helpers
// ---------------------------------------------------------------------------
__device__ __forceinline__ void mbar_init(uint32_t mbar, uint32_t cnt) {
    asm volatile("mbarrier.init.shared.b64 [%0], %1;" :: "r"(mbar), "r"(cnt) : "memory");
}
__device__ __forceinline__ void mbar_expect_tx(uint32_t mbar, uint32_t bytes) {
    asm volatile("mbarrier.arrive.expect_tx.shared.b64 _, [%0], %1;"
                 :: "r"(mbar), "r"(bytes) : "memory");
}
__device__ __forceinline__ void mbar_wait(uint32_t mbar, uint32_t phase) {
    asm volatile(
        "{\n\t"
        ".reg .pred P;\n\t"
        "WAIT_%=:\n\t"
        "mbarrier.try_wait.parity.acquire.cta.shared::cta.b64 P, [%0], %1, 0x989680;\n\t"
        "@P bra.uni DONE_%=;\n\t"
        "bra.uni WAIT_%=;\n\t"
        "DONE_%=:\n\t"
        "}"
        :: "r"(mbar), "r"(phase) : "memory");
}
__device__ __forceinline__ void bulk_g2s(uint32_t dst_smem, const void* src,
                                         uint32_t bytes, uint32_t mbar) {
    asm volatile(
        "cp.async.bulk.shared::cluster.global.mbarrier::complete_tx::bytes "
        "[%0], [%1], %2, [%3];"
        :: "r"(dst_smem), "l"(src), "r"(bytes), "r"(mbar) : "memory");
}

// ---------------------------------------------------------------------------
// Kernel 1: out = x@(W_obj+W_skip) + r@W_rel + biases ;  g_y = x@W_nobj+b_nobj
// ---------------------------------------------------------------------------
__global__ __launch_bounds__(128) void k1_proj(
    const float* __restrict__ x, const float* __restrict__ r,
    const float* __restrict__ W_obj, const float* __restrict__ b_obj,
    const float* __restrict__ W_nobj, const float* __restrict__ b_nobj,
    const float* __restrict__ W_rel, const float* __restrict__ b_rel,
    const float* __restrict__ W_skip, const float* __restrict__ b_skip,
    float* __restrict__ out)
{
    __shared__ float Wc[D * D];
    __shared__ float Wn[D * D];
    __shared__ float Wr[D * D];

    const int t = threadIdx.x;
    for (int e = t; e < D * D; e += 128) {
        Wc[e] = W_obj[e] + W_skip[e];
        Wn[e] = W_nobj[e];
        Wr[e] = W_rel[e];
    }
    __syncthreads();

    const int row = blockIdx.x * 16 + (t >> 3);
    const int d0 = (t & 7) * 8;

    float ab[8], ay[8];
#pragma unroll
    for (int q = 0; q < 8; q++) { ab[q] = 0.f; ay[q] = 0.f; }

    const float4* xp = (const float4*)(x + row * D);
    const float4* rp = (const float4*)(r + row * D);

#pragma unroll 4
    for (int k4 = 0; k4 < D / 4; k4++) {
        const float4 xq = xp[k4];
        const float4 rq = rp[k4];
        const float xv[4] = {xq.x, xq.y, xq.z, xq.w};
        const float rv[4] = {rq.x, rq.y, rq.z, rq.w};
#pragma unroll
        for (int u = 0; u < 4; u++) {
            const int k = k4 * 4 + u;
            const float4 c0 = *(const float4*)&Wc[k * D + d0];
            const float4 c1 = *(const float4*)&Wc[k * D + d0 + 4];
            const float4 n0 = *(const float4*)&Wn[k * D + d0];
            const float4 n1 = *(const float4*)&Wn[k * D + d0 + 4];
            const float4 q0 = *(const float4*)&Wr[k * D + d0];
            const float4 q1 = *(const float4*)&Wr[k * D + d0 + 4];
            const float cc[8] = {c0.x,c0.y,c0.z,c0.w,c1.x,c1.y,c1.z,c1.w};
            const float nn[8] = {n0.x,n0.y,n0.z,n0.w,n1.x,n1.y,n1.z,n1.w};
            const float qq[8] = {q0.x,q0.y,q0.z,q0.w,q1.x,q1.y,q1.z,q1.w};
#pragma unroll
            for (int q = 0; q < 8; q++) {
                ab[q] += xv[u] * cc[q] + rv[u] * qq[q];
                ay[q] += xv[u] * nn[q];
            }
        }
    }

    float4 o0, o1, y0, y1;
    o0.x = ab[0]+b_obj[d0+0]+b_skip[d0+0]+b_rel[d0+0];
    o0.y = ab[1]+b_obj[d0+1]+b_skip[d0+1]+b_rel[d0+1];
    o0.z = ab[2]+b_obj[d0+2]+b_skip[d0+2]+b_rel[d0+2];
    o0.w = ab[3]+b_obj[d0+3]+b_skip[d0+3]+b_rel[d0+3];
    o1.x = ab[4]+b_obj[d0+4]+b_skip[d0+4]+b_rel[d0+4];
    o1.y = ab[5]+b_obj[d0+5]+b_skip[d0+5]+b_rel[d0+5];
    o1.z = ab[6]+b_obj[d0+6]+b_skip[d0+6]+b_rel[d0+6];
    o1.w = ab[7]+b_obj[d0+7]+b_skip[d0+7]+b_rel[d0+7];
    y0.x = ay[0]+b_nobj[d0+0]; y0.y = ay[1]+b_nobj[d0+1];
    y0.z = ay[2]+b_nobj[d0+2]; y0.w = ay[3]+b_nobj[d0+3];
    y1.x = ay[4]+b_nobj[d0+4]; y1.y = ay[5]+b_nobj[d0+5];
    y1.z = ay[6]+b_nobj[d0+6]; y1.w = ay[7]+b_nobj[d0+7];
    float4* op = (float4*)(out + row * D + d0);
    float4* yp = (float4*)(g_y + row * D + d0);
    op[0] = o0; op[1] = o1;
    yp[0] = y0; yp[1] = y1;
}

// ---------------------------------------------------------------------------
// Kernel 2a v6: TMA-staged A scan. A bytes never touch registers via LDG —
// cp.async.bulk streams 16 KB row-segments into a double-buffered smem ring
// (mbarrier expect_tx completion), threads predicate from smem (conflict-free
// interleaved LDS.32) into per-thread register masks, masks stored coalesced.
// CTA = 32 rows x 4096 cols; thread owns cols {t + 256k, k<16}; bit = row.
// ---------------------------------------------------------------------------
__global__ __launch_bounds__(256) void k2a_scan(const float* __restrict__ A)
{
    extern __shared__ float sm[];
    float* buf[2] = { sm, sm + SCOLS };                    // 2 x 16 KB
    unsigned* msk = (unsigned*)(sm + 2 * SCOLS);           // 16 KB
    const uint32_t sbase = (uint32_t)__cvta_generic_to_shared(sm);
    const uint32_t mb0 = sbase + 3 * SEG_BYTES;            // two mbarriers
    const uint32_t mb1 = mb0 + 8;

    const int t = threadIdx.x;
    const int c32 = blockIdx.y;                            // 32-row chunk 0..255
    const int cbase = blockIdx.x * SCOLS;

    if (t == 0) {
        mbar_init(mb0, 1);
        mbar_init(mb1, 1);
        asm volatile("fence.proxy.async.shared::cta;" ::: "memory");
    }
    __syncthreads();

    const float* Abase = A + (size_t)c32 * 32 * N + cbase;

    // prologue: stage rows 0 and 1
    if (t == 0) {
        mbar_expect_tx(mb0, SEG_BYTES);
        bulk_g2s(sbase, Abase, SEG_BYTES, mb0);
        mbar_expect_tx(mb1, SEG_BYTES);
        bulk_g2s(sbase + SEG_BYTES, Abase + (size_t)N, SEG_BYTES, mb1);
    }

    unsigned mreg[16];
#pragma unroll
    for (int k = 0; k < 16; k++) mreg[k] = 0u;

    int ph0 = 0, ph1 = 0;
    for (int r = 0; r < SROWS; r++) {
        if (r & 1) { mbar_wait(mb1, ph1); ph1 ^= 1; }
        else       { mbar_wait(mb0, ph0); ph0 ^= 1; }

        const float* b = buf[r & 1];
        const unsigned bit = 1u << r;
#pragma unroll
        for (int k = 0; k < 16; k++) {
            const float v = b[t + 256 * k];                // bank t%32: conflict-free
            if (v != 0.0f) mreg[k] |= bit;
        }
        __syncthreads();                                   // buffer fully consumed
        if (r + 2 < SROWS && t == 0) {
            const uint32_t dst = sbase + (r & 1) * SEG_BYTES;
            const uint32_t mbr = (r & 1) ? mb1 : mb0;
            mbar_expect_tx(mbr, SEG_BYTES);
            bulk_g2s(dst, Abase + (size_t)(r + 2) * N, SEG_BYTES, mbr);
        }
    }

    // bounce masks through smem -> coalesced uint4 store
#pragma unroll
    for (int k = 0; k < 16; k++) msk[t + 256 * k] = mreg[k];
    __syncthreads();
    uint4* gm = (uint4*)(g_mask32 + (size_t)c32 * N + cbase);
    const uint4* ms4 = (const uint4*)msk;
#pragma unroll
    for (int e = 0; e < (SCOLS / 4) / 256; e++)            // 4 per thread
        gm[e * 256 + t] = ms4[e * 256 + t];
}

// ---------------------------------------------------------------------------
// Kernel 2b: gather. CTA = 128 rows (i) x one j-split. Per chunk: stage y
// (32 KB), warp walks its 32 rows via 4 broadcast mask words + ffs,
// lane owns a d-pair; conflict-free LDS.64; register accumulators.
// ---------------------------------------------------------------------------
__global__ __launch_bounds__(128, 4) void k2b_gather()
{
    __shared__ float y_s[CJ * D];   // 32 KB

    const int t = threadIdx.x;
    const int w = t >> 5, lane = t & 31;
    const int i_base = blockIdx.x * TIB;
    const int jy = blockIdx.y;
    const size_t j_base = (size_t)jy * JRANGE;

    float accx[32], accy[32];
#pragma unroll
    for (int il = 0; il < 32; il++) { accx[il] = 0.f; accy[il] = 0.f; }

    for (int c = 0; c < NCHUNK; c++) {
        {
            const float4* ys = (const float4*)(g_y + (j_base + c * CJ) * D);
            float4* yd = (float4*)y_s;
#pragma unroll
            for (int e = 0; e < (CJ * D / 4) / 128; e++)   // 16
                yd[e * 128 + t] = ys[e * 128 + t];
        }
        __syncthreads();

        const int chunk = jy * NCHUNK + c;                 // 128-j chunk index
        const unsigned* mbase = g_mask32 + (size_t)chunk * 4 * N + i_base;
        const float2* y2 = (const float2*)y_s;

#pragma unroll 4
        for (int il = 0; il < 32; il++) {
            const int iloc = (w << 5) | il;
            unsigned mwords[4];
#pragma unroll
            for (int k4 = 0; k4 < 4; k4++)                 // broadcast loads
                mwords[k4] = __ldg(mbase + (size_t)k4 * N + iloc);
            float ax = 0.f, ay = 0.f;
#pragma unroll
            for (int k4 = 0; k4 < 4; k4++) {
                unsigned mm = mwords[k4];
                while (mm) {
                    const int b = __ffs(mm) - 1;
                    mm &= mm - 1;
                    const float2 v = y2[(k4 * 32 + b) * 32 + lane];
                    ax += v.x; ay += v.y;
                }
            }
            accx[il] += ax;
            accy[il] += ay;
        }
        __syncthreads();   // y_s free for restage
    }

#pragma unroll
    for (int il = 0; il < 32; il++) {
        const int i = i_base + (w << 5) + il;
        ((float2*)&g_part[jy][(size_t)i * D])[lane] = make_float2(accx[il], accy[il]);
    }
}

// ---------------------------------------------------------------------------
// Kernel 3: out += sum over the JS partials (fixed order -> deterministic)
// ---------------------------------------------------------------------------
__global__ __launch_bounds__(256) void k3_reduce(float* __restrict__ out)
{
    const int g = blockIdx.x * blockDim.x + threadIdx.x;
    float4 v = ((const float4*)out)[g];
#pragma unroll
    for (int s = 0; s < JS; s++) {
        const float4 p = ((const float4*)(&g_part[s][0]))[g];
        v.x += p.x; v.y += p.y; v.z += p.z; v.w += p.w;
    }
    ((float4*)out)[g] = v;
}

// ---------------------------------------------------------------------------
extern "C" void kernel_launch(void* const* d_in, const int* in_sizes, int n_in,
                              void* d_out, int out_size)
{
    const float* x      = (const float*)d_in[0];
    const float* r      = (const float*)d_in[1];
    const float* A      = (const float*)d_in[2];
    const float* W_obj  = (const float*)d_in[3];
    const float* b_obj  = (const float*)d_in[4];
    const float* W_nobj = (const float*)d_in[5];
    const float* b_nobj = (const float*)d_in[6];
    const float* W_rel  = (const float*)d_in[7];
    const float* b_rel  = (const float*)d_in[8];
    const float* W_skip = (const float*)d_in[9];
    const float* b_skip = (const float*)d_in[10];
    // d_in[11]/d_in[12] (Wa_w, Wa_b) provably cancel: softmax rows sum to 1,
    // so the attention term is the identity on `aggregated`.
    float* out = (float*)d_out;

    const size_t sm2a = 3 * SEG_BYTES + 32;   // 2 ring buffers + mask + mbarriers
    cudaFuncSetAttribute(k2a_scan, cudaFuncAttributeMaxDynamicSharedMemorySize, (int)sm2a);

    k2a_scan<<<dim3(N / SCOLS, NC32), 256, sm2a>>>(A);    // longest stream first
    k1_proj<<<N / 16, 128>>>(x, r, W_obj, b_obj, W_nobj, b_nobj,
                             W_rel, b_rel, W_skip, b_skip, out);
    k2b_gather<<<dim3(N / TIB, JS), 128>>>();
    k3_reduce<<<(N * D / 4) / 256, 256>>>(out);
}